// round 7
// baseline (speedup 1.0000x reference)
#include <cuda_runtime.h>
#include <cuda_bf16.h>
#include <cstdint>
#include <math.h>

#define NF 512
#define NFIELD 30
#define KDIM 40
#define MT 64           // rows per CTA
#define NT 128          // n per sweep (4 sweeps)
#define KC 64           // k per chunk
#define NTHREADS 256
#define NCHUNK 32       // 4 sweeps x 8 k-chunks

// ---- smem layout (bytes) ----
#define SM_X      0
#define SM_X_BYTES (MT * NF * 2)            // 65536
#define SM_B      (SM_X + SM_X_BYTES)
#define SM_B_SLOT (NT * KC * 2)             // 16384
#define SM_ACC    (SM_B + 3 * SM_B_SLOT)    // 114688
#define SM_TOT    (SM_ACC + MT * 4)         // 114944

// Precomputed interaction matrix G = 0.5*C, zero diag, bf16, symmetric.
__device__ __nv_bfloat16 g_G[NF * NF];

// ---------------- helpers ----------------
__device__ __forceinline__ uint32_t smem_u32(const void* p) {
    uint32_t a;
    asm("{ .reg .u64 t; cvta.to.shared.u64 t, %1; cvt.u32.u64 %0, t; }" : "=r"(a) : "l"(p));
    return a;
}
__device__ __forceinline__ uint32_t sw128(uint32_t b) { return b ^ ((b >> 3) & 0x70); }
// X tile: blocked atoms (8 rows x 64 bf16 = 1024B); atom = (r>>3) + (k>>6)*8
__device__ __forceinline__ uint32_t aByte(int r, int k) {
    return (uint32_t)((((r >> 3) + (k >> 6) * 8) << 10) + ((r & 7) << 7) + ((k & 63) << 1));
}
__device__ __forceinline__ void ldsm4(uint32_t* r, uint32_t addr) {
    asm volatile("ldmatrix.sync.aligned.m8n8.x4.shared.b16 {%0,%1,%2,%3}, [%4];"
                 : "=r"(r[0]), "=r"(r[1]), "=r"(r[2]), "=r"(r[3]) : "r"(addr));
}
__device__ __forceinline__ void mma16816(float* c, const uint32_t* a, const uint32_t* b) {
    asm volatile(
        "mma.sync.aligned.m16n8k16.row.col.f32.bf16.bf16.f32 "
        "{%0,%1,%2,%3}, {%4,%5,%6,%7}, {%8,%9}, {%0,%1,%2,%3};"
        : "+f"(c[0]), "+f"(c[1]), "+f"(c[2]), "+f"(c[3])
        : "r"(a[0]), "r"(a[1]), "r"(a[2]), "r"(a[3]), "r"(b[0]), "r"(b[1]));
}
__device__ __forceinline__ void cp16(uint32_t dst, const void* src) {
    asm volatile("cp.async.cg.shared.global [%0], [%1], 16;" :: "r"(dst), "l"(src) : "memory");
}
#define CP_COMMIT() asm volatile("cp.async.commit_group;" ::: "memory")

// ---------------------------------------------------------------------------
// Kernel 1: G symmetric — compute i>=j, write both mirrors.
// ---------------------------------------------------------------------------
__global__ void build_G_kernel(const float* __restrict__ v, const int* __restrict__ f2f) {
    int j = blockIdx.x;
    int i = threadIdx.x;
    if (i < j) return;
    int fj = __ldg(&f2f[j]);
    int fi = __ldg(&f2f[i]);
    const float4* a  = reinterpret_cast<const float4*>(v + ((size_t)i * NFIELD + fj) * KDIM);
    const float4* bp = reinterpret_cast<const float4*>(v + ((size_t)j * NFIELD + fi) * KDIM);
    float s = 0.f;
#pragma unroll
    for (int t = 0; t < KDIM / 4; t++) {
        float4 av = a[t], bv = bp[t];
        s = fmaf(av.x, bv.x, s);
        s = fmaf(av.y, bv.y, s);
        s = fmaf(av.z, bv.z, s);
        s = fmaf(av.w, bv.w, s);
    }
    s *= 0.5f;
    if (i == j) s = 0.f;
    __nv_bfloat16 h = __float2bfloat16(s);
    g_G[(size_t)j * NF + i] = h;
    g_G[(size_t)i * NF + j] = h;
}

// ---------------------------------------------------------------------------
// Kernel 2: HMMA quadratic form, 8 warps, 2 CTAs/SM, k-split warp pairs.
//   wk = wid&1      : k-half of each 64-k chunk (ks 0-1 vs 2-3)
//   wm = (wid>>1)&1 : 2 x 32 rows
//   wn = wid>>2     : 2 x 64 cols of NT=128
//   Each warp: m32 x n64 partial accumulator over its k-half; the shared
//   atomicAdd epilogue merges the two k-halves. Only wk==0 warps fold w1 in.
// ---------------------------------------------------------------------------
__global__ __launch_bounds__(NTHREADS, 2)
void ffm_hmma_kernel(const float* __restrict__ X, const float* __restrict__ w1g,
                     const float* __restrict__ bg, float* __restrict__ out) {
    extern __shared__ __align__(1024) char smem[];
    const int tid  = threadIdx.x;
    const int lane = tid & 31;
    const int wid  = tid >> 5;
    const int wk   = wid & 1;
    const int wm   = (wid >> 1) & 1;
    const int wn   = wid >> 2;

    uint32_t sb = smem_u32(smem);
    float* accs = reinterpret_cast<float*>(smem + SM_ACC);
    if (tid < MT) accs[tid] = 0.f;

    // ---- G chunk stager: chunk t -> jt = t>>3 (n quarter), kc = t&7 ----
    auto issue = [&](int t) {
        int jt = t >> 3, kc = t & 7;
        uint32_t slot = sb + SM_B + (t % 3) * SM_B_SLOT;
        const __nv_bfloat16* gb = g_G + (size_t)jt * NT * NF + kc * KC;
#pragma unroll
        for (int i = 0; i < 4; i++) {
            int flat = tid + i * NTHREADS;       // 0..1023
            int n = flat >> 3, kq = flat & 7;
            uint32_t byte = ((uint32_t)(n >> 3) << 10) + ((n & 7) << 7) + (kq << 4);
            cp16(slot + sw128(byte), gb + (size_t)n * NF + kq * 8);
        }
        CP_COMMIT();
    };
    issue(0);
    issue(1);

    // ---- X prologue: 64 x 512 f32 -> bf16, swizzled blocked atoms ----
    const float4* Xg = reinterpret_cast<const float4*>(X + (size_t)blockIdx.x * MT * NF);
#pragma unroll 4
    for (int it = 0; it < 32; it++) {
        int f = tid + it * NTHREADS;
        int r = f >> 7;             // 128 float4 per row
        int k = (f & 127) * 4;
        float4 x4 = Xg[f];
        __nv_bfloat162 lo, hi;
        lo.x = __float2bfloat16(x4.x); lo.y = __float2bfloat16(x4.y);
        hi.x = __float2bfloat16(x4.z); hi.y = __float2bfloat16(x4.w);
        uint2 u;
        u.x = *reinterpret_cast<uint32_t*>(&lo);
        u.y = *reinterpret_cast<uint32_t*>(&hi);
        *reinterpret_cast<uint2*>(smem + SM_X + sw128(aByte(r, k))) = u;
    }

    // ---- per-lane ldsm address constants (swizzle folded: disjoint bits) ----
    uint32_t koffA[2], koffB[2];
#pragma unroll
    for (int ksi = 0; ksi < 2; ksi++) {
        int ks = wk * 2 + ksi;
        koffA[ksi] = ((uint32_t)((lane >> 4) << 4) | (ks << 5)) ^ ((lane & 7) << 4);
        koffB[ksi] = ((uint32_t)(((lane >> 3) & 1) << 4) | (ks << 5)) ^ ((lane & 7) << 4);
    }
    uint32_t aRowB[2], bRowB[4];
#pragma unroll
    for (int mf = 0; mf < 2; mf++)
        aRowB[mf] = sb + SM_X +
            (uint32_t)(((wm * 4 + mf * 2 + ((lane >> 3) & 1)) << 10) | ((lane & 7) << 7));
#pragma unroll
    for (int nf = 0; nf < 4; nf++)
        bRowB[nf] = (uint32_t)(((wn * 8 + nf * 2 + ((lane >> 4) & 1)) << 10) | ((lane & 7) << 7));

    float acc[2][8][4];
    const float bias0 = bg[0];

#pragma unroll 1
    for (int t = 0; t < NCHUNK; t++) {
        if (t < NCHUNK - 1) asm volatile("cp.async.wait_group 1;" ::: "memory");
        else                asm volatile("cp.async.wait_group 0;" ::: "memory");
        __syncthreads();   // chunk t visible to all; all warps done with chunk t-1
        if (t < NCHUNK - 2) issue(t + 2);

        if ((t & 7) == 0) {
            // init accumulators; only k-half 0 folds the linear term in
            int jt = t >> 3;
#pragma unroll
            for (int nf8 = 0; nf8 < 8; nf8++) {
                float w0 = 0.f, w1v = 0.f;
                if (wk == 0) {
                    int c = jt * NT + wn * 64 + nf8 * 8 + (lane & 3) * 2;
                    w0  = __ldg(&w1g[c]);
                    w1v = __ldg(&w1g[c + 1]);
                }
#pragma unroll
                for (int mf = 0; mf < 2; mf++) {
                    acc[mf][nf8][0] = w0;  acc[mf][nf8][1] = w1v;
                    acc[mf][nf8][2] = w0;  acc[mf][nf8][3] = w1v;
                }
            }
        }

        uint32_t slot = sb + SM_B + (uint32_t)(t % 3) * SM_B_SLOT;
        uint32_t aB[2], bB[4];
#pragma unroll
        for (int mf = 0; mf < 2; mf++) aB[mf] = aRowB[mf] + ((uint32_t)(t & 7) << 13);
#pragma unroll
        for (int nf = 0; nf < 4; nf++) bB[nf] = slot + bRowB[nf];

#pragma unroll
        for (int ksi = 0; ksi < 2; ksi++) {
            uint32_t a[2][4], b[4][4];
#pragma unroll
            for (int mf = 0; mf < 2; mf++) ldsm4(a[mf], aB[mf] + koffA[ksi]);
#pragma unroll
            for (int nf = 0; nf < 4; nf++) ldsm4(b[nf], bB[nf] + koffB[ksi]);
#pragma unroll
            for (int mf = 0; mf < 2; mf++) {
#pragma unroll
                for (int nf = 0; nf < 4; nf++) {
                    mma16816(acc[mf][2 * nf],     a[mf], &b[nf][0]);
                    mma16816(acc[mf][2 * nf + 1], a[mf], &b[nf][2]);
                }
            }
        }

        if ((t & 7) == 7) {
            // ---- epilogue: sum += acc . x (each k-half adds its partial) ----
            int jt = t >> 3;
#pragma unroll
            for (int mf = 0; mf < 2; mf++) {
                int r0 = wm * 32 + mf * 16 + (lane >> 2);
                int r1 = r0 + 8;
                float pA = 0.f, pB = 0.f;
#pragma unroll
                for (int nf8 = 0; nf8 < 8; nf8++) {
                    int c = jt * NT + wn * 64 + nf8 * 8 + (lane & 3) * 2;
                    uint32_t xa = *reinterpret_cast<uint32_t*>(smem + SM_X + sw128(aByte(r0, c)));
                    uint32_t xb = *reinterpret_cast<uint32_t*>(smem + SM_X + sw128(aByte(r1, c)));
                    float x0 = __uint_as_float(xa << 16);
                    float x1 = __uint_as_float(xa & 0xffff0000u);
                    float y0 = __uint_as_float(xb << 16);
                    float y1 = __uint_as_float(xb & 0xffff0000u);
                    pA = fmaf(acc[mf][nf8][0], x0, pA);
                    pA = fmaf(acc[mf][nf8][1], x1, pA);
                    pB = fmaf(acc[mf][nf8][2], y0, pB);
                    pB = fmaf(acc[mf][nf8][3], y1, pB);
                }
                pA += __shfl_xor_sync(0xffffffffu, pA, 1);
                pA += __shfl_xor_sync(0xffffffffu, pA, 2);
                pB += __shfl_xor_sync(0xffffffffu, pB, 1);
                pB += __shfl_xor_sync(0xffffffffu, pB, 2);
                if ((lane & 3) == 0) {
                    atomicAdd(&accs[r0], pA);
                    atomicAdd(&accs[r1], pB);
                }
            }
        }
    }

    __syncthreads();
    if (tid < MT) {
        float logit = accs[tid] + bias0;
        out[blockIdx.x * MT + tid] = 1.f / (1.f + expf(-logit));
    }
}

// ---------------------------------------------------------------------------
// kernel_launch
//   inputs: X [B,512] f32, w1 [512,1] f32, b [1] f32,
//           v [512,30,40] f32, feature2field [512] i32 ; output [B] f32
// ---------------------------------------------------------------------------
extern "C" void kernel_launch(void* const* d_in, const int* in_sizes, int n_in,
                              void* d_out, int out_size) {
    const float* X   = (const float*)d_in[0];
    const float* w1  = (const float*)d_in[1];
    const float* b   = (const float*)d_in[2];
    const float* v   = (const float*)d_in[3];
    const int*   f2f = (const int*)d_in[4];
    float* out = (float*)d_out;
    (void)n_in; (void)out_size;

    int Brows = in_sizes[0] / NF;

    static bool attr_set = false;
    if (!attr_set) {
        cudaFuncSetAttribute(ffm_hmma_kernel,
                             cudaFuncAttributeMaxDynamicSharedMemorySize, SM_TOT);
        attr_set = true;
    }

    build_G_kernel<<<NF, NF>>>(v, f2f);
    ffm_hmma_kernel<<<Brows / MT, NTHREADS, SM_TOT>>>(X, w1, b, out);
}

// round 8
// speedup vs baseline: 1.0540x; 1.0540x over previous
#include <cuda_runtime.h>
#include <cuda_bf16.h>
#include <cstdint>
#include <math.h>

#define NF 512
#define NFIELD 30
#define KDIM 40
#define MT 128          // rows per CTA
#define NT 256          // n per sweep (2 sweeps)
#define KC 64           // k per chunk
#define NTHREADS 512
#define NCHUNK 16       // 2 sweeps x 8 k-chunks

// ---- smem layout (bytes) ----
#define SM_X      0
#define SM_X_BYTES (MT * NF * 2)            // 131072
#define SM_B      (SM_X + SM_X_BYTES)
#define SM_B_SLOT (NT * KC * 2)             // 32768
#define SM_ACC    (SM_B + 3 * SM_B_SLOT)    // 229376
#define SM_TOT    (SM_ACC + MT * 4)         // 229888

// Precomputed interaction matrix G = 0.5*C, zero diag, bf16, symmetric.
__device__ __nv_bfloat16 g_G[NF * NF];

// ---------------- helpers ----------------
__device__ __forceinline__ uint32_t smem_u32(const void* p) {
    uint32_t a;
    asm("{ .reg .u64 t; cvta.to.shared.u64 t, %1; cvt.u32.u64 %0, t; }" : "=r"(a) : "l"(p));
    return a;
}
__device__ __forceinline__ uint32_t sw128(uint32_t b) { return b ^ ((b >> 3) & 0x70); }
// X tile: blocked atoms (8 rows x 64 bf16 = 1024B); atom = (r>>3) + (k>>6)*16
__device__ __forceinline__ uint32_t aByte(int r, int k) {
    return (uint32_t)((((r >> 3) + (k >> 6) * 16) << 10) + ((r & 7) << 7) + ((k & 63) << 1));
}
__device__ __forceinline__ void ldsm4(uint32_t* r, uint32_t addr) {
    asm volatile("ldmatrix.sync.aligned.m8n8.x4.shared.b16 {%0,%1,%2,%3}, [%4];"
                 : "=r"(r[0]), "=r"(r[1]), "=r"(r[2]), "=r"(r[3]) : "r"(addr));
}
__device__ __forceinline__ void mma16816(float* c, const uint32_t* a, const uint32_t* b) {
    asm volatile(
        "mma.sync.aligned.m16n8k16.row.col.f32.bf16.bf16.f32 "
        "{%0,%1,%2,%3}, {%4,%5,%6,%7}, {%8,%9}, {%0,%1,%2,%3};"
        : "+f"(c[0]), "+f"(c[1]), "+f"(c[2]), "+f"(c[3])
        : "r"(a[0]), "r"(a[1]), "r"(a[2]), "r"(a[3]), "r"(b[0]), "r"(b[1]));
}
__device__ __forceinline__ void cp16(uint32_t dst, const void* src) {
    asm volatile("cp.async.cg.shared.global [%0], [%1], 16;" :: "r"(dst), "l"(src) : "memory");
}
#define CP_COMMIT() asm volatile("cp.async.commit_group;" ::: "memory")

// ---------------------------------------------------------------------------
// Kernel 1: G symmetric — compute i>=j, write both mirrors.
// ---------------------------------------------------------------------------
__global__ void build_G_kernel(const float* __restrict__ v, const int* __restrict__ f2f) {
    int j = blockIdx.x;
    int i = threadIdx.x;
    if (i < j) return;
    int fj = __ldg(&f2f[j]);
    int fi = __ldg(&f2f[i]);
    const float4* a  = reinterpret_cast<const float4*>(v + ((size_t)i * NFIELD + fj) * KDIM);
    const float4* bp = reinterpret_cast<const float4*>(v + ((size_t)j * NFIELD + fi) * KDIM);
    float s = 0.f;
#pragma unroll
    for (int t = 0; t < KDIM / 4; t++) {
        float4 av = a[t], bv = bp[t];
        s = fmaf(av.x, bv.x, s);
        s = fmaf(av.y, bv.y, s);
        s = fmaf(av.z, bv.z, s);
        s = fmaf(av.w, bv.w, s);
    }
    s *= 0.5f;
    if (i == j) s = 0.f;
    __nv_bfloat16 h = __float2bfloat16(s);
    g_G[(size_t)j * NF + i] = h;
    g_G[(size_t)i * NF + j] = h;
}

// ---------------------------------------------------------------------------
// Kernel 2: HMMA quadratic form, 16 warps, warp tile m32 x n64.
//   R4 structure + software-pipelined fragments: ldsm for k-step ks+1 is
//   issued while the mma of k-step ks executes (double-buffered frags).
// ---------------------------------------------------------------------------
__global__ __launch_bounds__(NTHREADS, 1)
void ffm_hmma_kernel(const float* __restrict__ X, const float* __restrict__ w1g,
                     const float* __restrict__ bg, float* __restrict__ out) {
    extern __shared__ __align__(1024) char smem[];
    const int tid  = threadIdx.x;
    const int lane = tid & 31;
    const int wid  = tid >> 5;
    const int wm   = wid & 3;
    const int wn   = wid >> 2;

    uint32_t sb = smem_u32(smem);
    float* accs = reinterpret_cast<float*>(smem + SM_ACC);
    if (tid < MT) accs[tid] = 0.f;

    // ---- G chunk stager: chunk t -> jt = t>>3 (n-half), kc = t&7 ----
    auto issue = [&](int t) {
        int jt = t >> 3, kc = t & 7;
        uint32_t slot = sb + SM_B + (t % 3) * SM_B_SLOT;
        const __nv_bfloat16* gb = g_G + (size_t)jt * NT * NF + kc * KC;
#pragma unroll
        for (int i = 0; i < 4; i++) {
            int flat = tid + i * NTHREADS;       // 0..2047
            int n = flat >> 3, kq = flat & 7;
            uint32_t byte = ((uint32_t)(n >> 3) << 10) + ((n & 7) << 7) + (kq << 4);
            cp16(slot + sw128(byte), gb + (size_t)n * NF + kq * 8);
        }
        CP_COMMIT();
    };
    issue(0);
    issue(1);

    // ---- X prologue: 128 x 512 f32 -> bf16, swizzled blocked atoms ----
    const float4* Xg = reinterpret_cast<const float4*>(X + (size_t)blockIdx.x * MT * NF);
#pragma unroll 4
    for (int it = 0; it < 32; it++) {
        int f = tid + it * NTHREADS;
        int r = f >> 7;             // 128 float4 per row
        int k = (f & 127) * 4;
        float4 x4 = Xg[f];
        __nv_bfloat162 lo, hi;
        lo.x = __float2bfloat16(x4.x); lo.y = __float2bfloat16(x4.y);
        hi.x = __float2bfloat16(x4.z); hi.y = __float2bfloat16(x4.w);
        uint2 u;
        u.x = *reinterpret_cast<uint32_t*>(&lo);
        u.y = *reinterpret_cast<uint32_t*>(&hi);
        *reinterpret_cast<uint2*>(smem + SM_X + sw128(aByte(r, k))) = u;
    }

    // ---- per-lane ldsm address constants (swizzle folded: disjoint bits) ----
    uint32_t koffA[4], koffB[4];
#pragma unroll
    for (int ks = 0; ks < 4; ks++) {
        koffA[ks] = ((uint32_t)((lane >> 4) << 4) | (ks << 5)) ^ ((lane & 7) << 4);
        koffB[ks] = ((uint32_t)(((lane >> 3) & 1) << 4) | (ks << 5)) ^ ((lane & 7) << 4);
    }
    uint32_t aRowB[2], bRowB[4];
#pragma unroll
    for (int mf = 0; mf < 2; mf++)
        aRowB[mf] = sb + SM_X +
            (uint32_t)(((wm * 4 + mf * 2 + ((lane >> 3) & 1)) << 10) | ((lane & 7) << 7));
#pragma unroll
    for (int nf = 0; nf < 4; nf++)
        bRowB[nf] = (uint32_t)(((wn * 8 + nf * 2 + ((lane >> 4) & 1)) << 10) | ((lane & 7) << 7));

    float acc[2][8][4];
    const float bias0 = bg[0];

#pragma unroll 1
    for (int t = 0; t < NCHUNK; t++) {
        if (t < NCHUNK - 1) asm volatile("cp.async.wait_group 1;" ::: "memory");
        else                asm volatile("cp.async.wait_group 0;" ::: "memory");
        __syncthreads();   // chunk t visible to all; all warps done with chunk t-1
        if (t < NCHUNK - 2) issue(t + 2);

        if ((t & 7) == 0) {
            // init accumulators with w1 (folds linear term in)
            int jt = t >> 3;
#pragma unroll
            for (int nf8 = 0; nf8 < 8; nf8++) {
                int c = jt * NT + wn * 64 + nf8 * 8 + (lane & 3) * 2;
                float w0 = __ldg(&w1g[c]), w1v = __ldg(&w1g[c + 1]);
#pragma unroll
                for (int mf = 0; mf < 2; mf++) {
                    acc[mf][nf8][0] = w0;  acc[mf][nf8][1] = w1v;
                    acc[mf][nf8][2] = w0;  acc[mf][nf8][3] = w1v;
                }
            }
        }

        uint32_t slot = sb + SM_B + (uint32_t)(t % 3) * SM_B_SLOT;
        uint32_t aB[2], bB[4];
#pragma unroll
        for (int mf = 0; mf < 2; mf++) aB[mf] = aRowB[mf] + ((uint32_t)(t & 7) << 14);
#pragma unroll
        for (int nf = 0; nf < 4; nf++) bB[nf] = slot + bRowB[nf];

        // ---- software-pipelined k-steps: prefetch ks+1 while mma(ks) ----
        uint32_t a[2][2][4], b[2][4][4];
#pragma unroll
        for (int mf = 0; mf < 2; mf++) ldsm4(a[0][mf], aB[mf] + koffA[0]);
#pragma unroll
        for (int nf = 0; nf < 4; nf++) ldsm4(b[0][nf], bB[nf] + koffB[0]);

#pragma unroll
        for (int ks = 0; ks < 4; ks++) {
            const int cur = ks & 1;
            const int nxt = cur ^ 1;
            if (ks < 3) {
#pragma unroll
                for (int mf = 0; mf < 2; mf++) ldsm4(a[nxt][mf], aB[mf] + koffA[ks + 1]);
#pragma unroll
                for (int nf = 0; nf < 4; nf++) ldsm4(b[nxt][nf], bB[nf] + koffB[ks + 1]);
            }
#pragma unroll
            for (int mf = 0; mf < 2; mf++) {
#pragma unroll
                for (int nf = 0; nf < 4; nf++) {
                    mma16816(acc[mf][2 * nf],     a[cur][mf], &b[cur][nf][0]);
                    mma16816(acc[mf][2 * nf + 1], a[cur][mf], &b[cur][nf][2]);
                }
            }
        }

        if ((t & 7) == 7) {
            // ---- epilogue for this n-sweep: sum += acc . x  (w1 already in) ----
            int jt = t >> 3;
#pragma unroll
            for (int mf = 0; mf < 2; mf++) {
                int r0 = wm * 32 + mf * 16 + (lane >> 2);
                int r1 = r0 + 8;
                float pA = 0.f, pB = 0.f;
#pragma unroll
                for (int nf8 = 0; nf8 < 8; nf8++) {
                    int c = jt * NT + wn * 64 + nf8 * 8 + (lane & 3) * 2;
                    uint32_t xa = *reinterpret_cast<uint32_t*>(smem + SM_X + sw128(aByte(r0, c)));
                    uint32_t xb = *reinterpret_cast<uint32_t*>(smem + SM_X + sw128(aByte(r1, c)));
                    float x0 = __uint_as_float(xa << 16);
                    float x1 = __uint_as_float(xa & 0xffff0000u);
                    float y0 = __uint_as_float(xb << 16);
                    float y1 = __uint_as_float(xb & 0xffff0000u);
                    pA = fmaf(acc[mf][nf8][0], x0, pA);
                    pA = fmaf(acc[mf][nf8][1], x1, pA);
                    pB = fmaf(acc[mf][nf8][2], y0, pB);
                    pB = fmaf(acc[mf][nf8][3], y1, pB);
                }
                pA += __shfl_xor_sync(0xffffffffu, pA, 1);
                pA += __shfl_xor_sync(0xffffffffu, pA, 2);
                pB += __shfl_xor_sync(0xffffffffu, pB, 1);
                pB += __shfl_xor_sync(0xffffffffu, pB, 2);
                if ((lane & 3) == 0) {
                    atomicAdd(&accs[r0], pA);
                    atomicAdd(&accs[r1], pB);
                }
            }
        }
    }

    __syncthreads();
    if (tid < MT) {
        float logit = accs[tid] + bias0;
        out[blockIdx.x * MT + tid] = 1.f / (1.f + expf(-logit));
    }
}

// ---------------------------------------------------------------------------
// kernel_launch
//   inputs: X [B,512] f32, w1 [512,1] f32, b [1] f32,
//           v [512,30,40] f32, feature2field [512] i32 ; output [B] f32
// ---------------------------------------------------------------------------
extern "C" void kernel_launch(void* const* d_in, const int* in_sizes, int n_in,
                              void* d_out, int out_size) {
    const float* X   = (const float*)d_in[0];
    const float* w1  = (const float*)d_in[1];
    const float* b   = (const float*)d_in[2];
    const float* v   = (const float*)d_in[3];
    const int*   f2f = (const int*)d_in[4];
    float* out = (float*)d_out;
    (void)n_in; (void)out_size;

    int Brows = in_sizes[0] / NF;

    static bool attr_set = false;
    if (!attr_set) {
        cudaFuncSetAttribute(ffm_hmma_kernel,
                             cudaFuncAttributeMaxDynamicSharedMemorySize, SM_TOT);
        attr_set = true;
    }

    build_G_kernel<<<NF, NF>>>(v, f2f);
    ffm_hmma_kernel<<<Brows / MT, NTHREADS, SM_TOT>>>(X, w1, b, out);
}